// round 1
// baseline (speedup 1.0000x reference)
#include <cuda_runtime.h>
#include <cuda_bf16.h>

// Problem constants
#define BB    8
#define SS    2048
#define DIN   2048
#define DOUT  2048
#define KK    16
#define RR    16

// Device scratch (no allocations allowed)
__device__ __align__(16) float g_Amix[BB * RR * DIN];        // [b][r][i]
__device__ __align__(16) float g_BP[BB * 8 * DOUT * 2];      // [b][rp][o][c]  (c: r=2rp+c pair)
__device__ __align__(16) float g_z[BB * SS * RR];            // [b][s][r]

// Packed fp32x2 FMA (Blackwell FFMA2). d = a*b + d elementwise on 2 packed f32.
__device__ __forceinline__ void ffma2(unsigned long long &d,
                                      unsigned long long a,
                                      unsigned long long b) {
    asm("fma.rn.f32x2 %0, %1, %2, %3;" : "=l"(d) : "l"(a), "l"(b), "l"(d));
}

__device__ __forceinline__ float2 unpack2(unsigned long long v) {
    float2 f;
    asm("mov.b64 {%0, %1}, %2;" : "=f"(f.x), "=f"(f.y) : "l"(v));
    return f;
}

// ---------------------------------------------------------------------------
// Kernel 1: mix banks with alpha.
//   g_Amix[b][r][i]      = sum_k alpha[b,k] * A_bank[k][r][i]
//   g_BP[b][rp][o][c]    = sum_k alpha[b,k] * B_bank[k][o][2*rp+c]
// 512 blocks x 256 threads = 131072 threads; first 65536 do A (float4 each),
// next 65536 do BP (float4 each).
// ---------------------------------------------------------------------------
__global__ void __launch_bounds__(256) mix_kernel(const float* __restrict__ alpha,
                                                  const float* __restrict__ Abank,
                                                  const float* __restrict__ Bbank) {
    int t = blockIdx.x * blockDim.x + threadIdx.x;
    if (t < 65536) {
        // A part: per b 16*2048/4 = 8192 float4s
        int b = t >> 13;
        int rem = t & 8191;
        int r = rem >> 9;
        int i = (rem & 511) << 2;
        const float* ab = Abank + r * DIN + i;
        const float* al = alpha + b * KK;
        float4 acc = make_float4(0.f, 0.f, 0.f, 0.f);
#pragma unroll
        for (int k = 0; k < KK; k++) {
            float a = al[k];
            float4 v = *(const float4*)(ab + (size_t)k * RR * DIN);
            acc.x += a * v.x; acc.y += a * v.y; acc.z += a * v.z; acc.w += a * v.w;
        }
        *(float4*)(g_Amix + ((b * RR + r) * DIN + i)) = acc;
    } else {
        int t2 = t - 65536;
        // BP part: per b 8*2048*2/4 = 8192 float4s
        int b = t2 >> 13;
        int rem = t2 & 8191;
        int rp = rem >> 10;
        int o = (rem & 1023) << 1;
        const float* bbase = Bbank + o * RR + 2 * rp;   // B_bank[k][o][2rp], k-stride = DOUT*RR
        const float* al = alpha + b * KK;
        float4 acc = make_float4(0.f, 0.f, 0.f, 0.f);
#pragma unroll
        for (int k = 0; k < KK; k++) {
            float a = al[k];
            float2 v0 = *(const float2*)(bbase + (size_t)k * DOUT * RR);       // (r=2rp, 2rp+1) @ o
            float2 v1 = *(const float2*)(bbase + (size_t)k * DOUT * RR + RR);  // @ o+1
            acc.x += a * v0.x; acc.y += a * v0.y;
            acc.z += a * v1.x; acc.w += a * v1.y;
        }
        *(float4*)(g_BP + (((b * 8 + rp) * DOUT) + o) * 2) = acc;
    }
}

// ---------------------------------------------------------------------------
// Kernel 2: z[b][s][r] = sum_i Amix[b][r][i] * h[b][s][i]
// 512 blocks (8 b x 64 s-tiles of 32), 256 threads = 8 warps x 4 s-rows.
// Lanes split i; accumulators are f32x2 with even/odd-i partials (natural
// pairing from the 128-bit loads — zero packing instructions).
// ---------------------------------------------------------------------------
__global__ void __launch_bounds__(256) z_kernel(const float* __restrict__ h) {
    __shared__ float red[8][64][17];   // [warp][v=s*16+r][lane/2 after one shfl round]

    int b = blockIdx.x >> 6;
    int stile = (blockIdx.x & 63) << 5;        // 32 s per CTA
    int warp = threadIdx.x >> 5;
    int lane = threadIdx.x & 31;
    int s0 = stile + warp * 4;

    const float* hp = h + ((size_t)(b * SS + s0) * DIN) + 4 * lane;
    const float* ap = g_Amix + (size_t)b * RR * DIN + 4 * lane;

    unsigned long long acc[4][16];
#pragma unroll
    for (int s = 0; s < 4; s++)
#pragma unroll
        for (int r = 0; r < 16; r++) acc[s][r] = 0ull;

#pragma unroll 1
    for (int c = 0; c < DIN / 128; c++) {
        int off = c * 128;
        ulonglong2 hv[4];
#pragma unroll
        for (int s = 0; s < 4; s++)
            hv[s] = *(const ulonglong2*)(hp + (size_t)s * DIN + off);
#pragma unroll
        for (int r = 0; r < 16; r++) {
            ulonglong2 av = *(const ulonglong2*)(ap + (size_t)r * DIN + off);
#pragma unroll
            for (int s = 0; s < 4; s++) {
                ffma2(acc[s][r], av.x, hv[s].x);
                ffma2(acc[s][r], av.y, hv[s].y);
            }
        }
    }

    // Reduce across lanes: collapse f32x2, one xor-16 shfl round, then smem.
#pragma unroll
    for (int s = 0; s < 4; s++) {
#pragma unroll
        for (int r = 0; r < 16; r++) {
            float2 p = unpack2(acc[s][r]);
            float sum = p.x + p.y;
            sum += __shfl_xor_sync(0xffffffffu, sum, 16);
            if (lane < 16) red[warp][s * 16 + r][lane] = sum;
        }
    }
    __syncthreads();

    // Phase 2: 512 rows (8 warps x 64 values), 16 partials each.
#pragma unroll
    for (int rr = 0; rr < 2; rr++) {
        int row = threadIdx.x + rr * 256;
        int w = row >> 6;
        int v = row & 63;
        float sum = 0.f;
#pragma unroll
        for (int j = 0; j < 16; j++) sum += red[w][v][j];
        int s = stile + w * 4 + (v >> 4);
        int r = v & 15;
        g_z[((size_t)b * SS + s) * RR + r] = sum;
    }
}

// ---------------------------------------------------------------------------
// Kernel 3: delta[b][s][o] = sum_r BP[b][r][o] * z[b][s][r]
// 4096 blocks = 8 b x 64 s-tiles(32) x 8 o-tiles(256); 128 threads = 4 warps x 8 s.
// Accumulators are f32x2 with even/odd-r partials; BP layout makes both
// operands naturally r-paired out of one LDG.128.
// ---------------------------------------------------------------------------
__global__ void __launch_bounds__(128) delta_kernel(float* __restrict__ out) {
    int ot = blockIdx.x & 7;
    int st = (blockIdx.x >> 3) & 63;
    int b = blockIdx.x >> 9;
    int warp = threadIdx.x >> 5;
    int lane = threadIdx.x & 31;
    int s0 = st * 32 + warp * 8;
    int o0 = ot * 256;

    // Preload z[s0..s0+7][0..15] as r-pairs (broadcast loads).
    unsigned long long zr[8][8];
    const float* zp = g_z + ((size_t)b * SS + s0) * RR;
#pragma unroll
    for (int s = 0; s < 8; s++) {
        const ulonglong2* zq = (const ulonglong2*)(zp + s * RR);
        ulonglong2 a0 = zq[0], a1 = zq[1], a2 = zq[2], a3 = zq[3];
        zr[s][0] = a0.x; zr[s][1] = a0.y; zr[s][2] = a1.x; zr[s][3] = a1.y;
        zr[s][4] = a2.x; zr[s][5] = a2.y; zr[s][6] = a3.x; zr[s][7] = a3.y;
    }

    const float* bp = g_BP + ((size_t)(b * 8) * DOUT + o0 + 2 * lane) * 2;
    float* op = out + ((size_t)(b * SS + s0)) * DOUT + o0 + 2 * lane;

#pragma unroll
    for (int ch = 0; ch < 4; ch++) {    // 64-o chunks; lane owns o = o0+ch*64+2*lane (+1)
        unsigned long long acc[8][2];
#pragma unroll
        for (int s = 0; s < 8; s++) { acc[s][0] = 0ull; acc[s][1] = 0ull; }

#pragma unroll
        for (int rp = 0; rp < 8; rp++) {
            ulonglong2 bv = *(const ulonglong2*)(bp + ((size_t)rp * DOUT + ch * 64) * 2);
#pragma unroll
            for (int s = 0; s < 8; s++) {
                ffma2(acc[s][0], bv.x, zr[s][rp]);   // o   (even/odd r partials)
                ffma2(acc[s][1], bv.y, zr[s][rp]);   // o+1
            }
        }

#pragma unroll
        for (int s = 0; s < 8; s++) {
            float2 r0 = unpack2(acc[s][0]);
            float2 r1 = unpack2(acc[s][1]);
            float2 w = make_float2(r0.x + r0.y, r1.x + r1.y);
            *(float2*)(op + (size_t)s * DOUT + ch * 64) = w;
        }
    }
}

// ---------------------------------------------------------------------------
extern "C" void kernel_launch(void* const* d_in, const int* in_sizes, int n_in,
                              void* d_out, int out_size) {
    const float* h     = (const float*)d_in[0];   // [8,2048,2048]
    const float* alpha = (const float*)d_in[1];   // [8,16]
    const float* Abank = (const float*)d_in[2];   // [16,16,2048]
    const float* Bbank = (const float*)d_in[3];   // [16,2048,16]
    float* out = (float*)d_out;                   // [8,2048,2048]

    mix_kernel<<<512, 256>>>(alpha, Abank, Bbank);
    z_kernel<<<512, 256>>>(h);
    delta_kernel<<<4096, 128>>>(out);
}